// round 1
// baseline (speedup 1.0000x reference)
#include <cuda_runtime.h>
#include <cuda_bf16.h>
#include <math.h>

#define NN      20000
#define NP1     20001
#define DD      256
#define NH      4
#define DH      64
#define NL      3
#define NE      320000
#define ELOC    (NE + 2*NN)      // 360000
#define QKVW    (3*DD)           // 768
#define FFH     (4*DD)           // 1024
#define ENC_NEG_INF 0x007FFFFFu

// ----------------------------- scratch (device globals; no allocs) ---------
__device__ float    g_h   [NP1 * DD];
__device__ float    g_sum [NP1 * DD];
__device__ float    g_qkv0[NP1 * QKVW];
__device__ float    g_qkv1[NP1 * QKVW];
__device__ float    g_num0[NP1 * DD];
__device__ float    g_num1[NP1 * DD];
__device__ float    g_att0[NP1 * DD];
__device__ float    g_att1[NP1 * DD];
__device__ float    g_ffn [NP1 * FFH];
__device__ unsigned g_menc0[NP1 * NH];
__device__ unsigned g_menc1[NP1 * NH];
__device__ float    g_den0[NP1 * NH];
__device__ float    g_den1[NP1 * NH];
__device__ int      g_src[ELOC];
__device__ int      g_dst[ELOC];

// ----------------------------- helpers -------------------------------------
__device__ __forceinline__ unsigned enc_f(float f) {
    unsigned u = __float_as_uint(f);
    return (u & 0x80000000u) ? ~u : (u | 0x80000000u);
}
__device__ __forceinline__ float dec_f(unsigned u) {
    return (u & 0x80000000u) ? __uint_as_float(u ^ 0x80000000u)
                             : __uint_as_float(~u);
}
static inline int cdiv(int a, int b) { return (a + b - 1) / b; }

// ----------------------------- elementwise kernels --------------------------
__global__ void k_build_h(const float* __restrict__ x, float* __restrict__ h) {
    int i = blockIdx.x * blockDim.x + threadIdx.x;
    if (i >= NP1 * DD) return;
    h[i] = (i < NN * DD) ? x[i] : 0.f;
}

__global__ void k_build_edges(const int* __restrict__ ei,
                              int* __restrict__ src, int* __restrict__ dst) {
    int i = blockIdx.x * blockDim.x + threadIdx.x;
    if (i >= ELOC) return;
    if (i < NE)            { src[i] = ei[i];          dst[i] = ei[NE + i]; }
    else if (i < NE + NN)  { src[i] = i - NE;         dst[i] = NN; }
    else                   { src[i] = NN;             dst[i] = i - NE - NN; }
}

__global__ void k_att_init(float* __restrict__ num, unsigned* __restrict__ menc,
                           float* __restrict__ den) {
    int i = blockIdx.x * blockDim.x + threadIdx.x;
    if (i < NP1 * DD) num[i] = 0.f;
    if (i < NP1 * NH) { menc[i] = ENC_NEG_INF; den[i] = 0.f; }
}

__global__ void k_copy(const float* __restrict__ s, float* __restrict__ d, int n) {
    int i = blockIdx.x * blockDim.x + threadIdx.x;
    if (i < n) d[i] = s[i];
}

__global__ void k_att_final(const float* __restrict__ num,
                            const float* __restrict__ den,
                            float* __restrict__ out) {
    int i = blockIdx.x * blockDim.x + threadIdx.x;
    if (i >= NP1 * DD) return;
    int row = i >> 8, col = i & 255;
    out[i] = num[i] / (den[row * NH + (col >> 6)] + 1e-16f);
}

// ----------------------------- attention (warp per edge) --------------------
__global__ void k_att_score(const float* __restrict__ qkv,
                            unsigned* __restrict__ menc,
                            const int* __restrict__ src,
                            const int* __restrict__ dst, int ne) {
    int warp = (blockIdx.x * blockDim.x + threadIdx.x) >> 5;
    int lane = threadIdx.x & 31;
    if (warp >= ne) return;
    int s = src[warp], d = dst[warp];
    int head = lane >> 3;
    int off  = head * DH + (lane & 7) * 8;
    const float4* qp = (const float4*)(qkv + (size_t)d * QKVW + off);
    const float4* kp = (const float4*)(qkv + (size_t)s * QKVW + DD + off);
    float4 q0 = qp[0], q1 = qp[1], k0 = kp[0], k1 = kp[1];
    float sum = q0.x*k0.x + q0.y*k0.y + q0.z*k0.z + q0.w*k0.w
              + q1.x*k1.x + q1.y*k1.y + q1.z*k1.z + q1.w*k1.w;
    sum += __shfl_down_sync(0xffffffffu, sum, 4);
    sum += __shfl_down_sync(0xffffffffu, sum, 2);
    sum += __shfl_down_sync(0xffffffffu, sum, 1);
    if ((lane & 7) == 0)
        atomicMax(&menc[d * NH + head], enc_f(sum * 0.125f));
}

__global__ void k_att_accum(const float* __restrict__ qkv,
                            const unsigned* __restrict__ menc,
                            float* __restrict__ den,
                            float* __restrict__ num,
                            const int* __restrict__ src,
                            const int* __restrict__ dst, int ne) {
    int warp = (blockIdx.x * blockDim.x + threadIdx.x) >> 5;
    int lane = threadIdx.x & 31;
    if (warp >= ne) return;
    int s = src[warp], d = dst[warp];
    int head = lane >> 3;
    int off  = head * DH + (lane & 7) * 8;
    const float4* qp = (const float4*)(qkv + (size_t)d * QKVW + off);
    const float4* kp = (const float4*)(qkv + (size_t)s * QKVW + DD + off);
    float4 q0 = qp[0], q1 = qp[1], k0 = kp[0], k1 = kp[1];
    float sum = q0.x*k0.x + q0.y*k0.y + q0.z*k0.z + q0.w*k0.w
              + q1.x*k1.x + q1.y*k1.y + q1.z*k1.z + q1.w*k1.w;
    sum += __shfl_down_sync(0xffffffffu, sum, 4);
    sum += __shfl_down_sync(0xffffffffu, sum, 2);
    sum += __shfl_down_sync(0xffffffffu, sum, 1);
    float tot = __shfl_sync(0xffffffffu, sum, lane & 24);
    float sc  = tot * 0.125f;
    float m   = dec_f(menc[d * NH + head]);
    float ex  = expf(sc - m);
    if ((lane & 7) == 0)
        atomicAdd(&den[d * NH + head], ex);
    const float4* vp = (const float4*)(qkv + (size_t)s * QKVW + 2*DD + off);
    float4 v0 = vp[0], v1 = vp[1];
    float* np = num + (size_t)d * DD + off;
    atomicAdd(np + 0, ex * v0.x);
    atomicAdd(np + 1, ex * v0.y);
    atomicAdd(np + 2, ex * v0.z);
    atomicAdd(np + 3, ex * v0.w);
    atomicAdd(np + 4, ex * v1.x);
    atomicAdd(np + 5, ex * v1.y);
    atomicAdd(np + 6, ex * v1.z);
    atomicAdd(np + 7, ex * v1.w);
}

// ----------------------------- layernorm ------------------------------------
__global__ void k_layernorm(const float* __restrict__ in,
                            const float* __restrict__ g,
                            const float* __restrict__ b,
                            float* __restrict__ out) {
    int row = blockIdx.x;
    int c   = threadIdx.x;         // 256 threads
    float v = in[row * DD + c];
    float s = v, sq = v * v;
    #pragma unroll
    for (int o = 16; o >= 1; o >>= 1) {
        s  += __shfl_down_sync(0xffffffffu, s,  o);
        sq += __shfl_down_sync(0xffffffffu, sq, o);
    }
    __shared__ float rs[8], rq[8];
    int w = c >> 5, lane = c & 31;
    if (lane == 0) { rs[w] = s; rq[w] = sq; }
    __syncthreads();
    __shared__ float mu_s, rstd_s;
    if (c == 0) {
        float ts = 0.f, tq = 0.f;
        #pragma unroll
        for (int i = 0; i < 8; i++) { ts += rs[i]; tq += rq[i]; }
        float mu  = ts * (1.f / DD);
        float var = tq * (1.f / DD) - mu * mu;
        mu_s = mu;
        rstd_s = rsqrtf(var + 1e-5f);
    }
    __syncthreads();
    out[row * DD + c] = (v - mu_s) * rstd_s * g[c] + b[c];
}

// ----------------------------- tiled SGEMM ----------------------------------
// C[nrow x M] = A[nrow x K] @ W[K x M] (+ bias) with fused epilogue.
#define BM 128
#define BN 128
#define BK 8
enum { EPI_STORE = 0, EPI_ADD = 1, EPI_GELU = 2 };

template <int EPI>
__global__ __launch_bounds__(256, 2)
void k_sgemm(const float* __restrict__ A, const float* __restrict__ W,
             const float* __restrict__ bias, float* __restrict__ C,
             int nrow, int K, int M) {
    __shared__ float As[BK][BM];
    __shared__ float Bs[BK][BN];
    int tid = threadIdx.x;
    int rowBase = blockIdx.y * BM;
    int colBase = blockIdx.x * BN;
    int tx = tid & 15, ty = tid >> 4;

    float acc[8][8];
    #pragma unroll
    for (int i = 0; i < 8; i++)
        #pragma unroll
        for (int j = 0; j < 8; j++) acc[i][j] = 0.f;

    int arow = tid >> 1;
    int acol = (tid & 1) * 4;
    int brow = tid >> 5;
    int bcol = (tid & 31) * 4;
    bool aval = (rowBase + arow) < nrow;
    const float* Aptr = A + (size_t)(rowBase + arow) * K + acol;
    const float* Wptr = W + (size_t)brow * M + colBase + bcol;

    for (int k0 = 0; k0 < K; k0 += BK) {
        float4 av = aval ? *(const float4*)(Aptr + k0) : make_float4(0,0,0,0);
        float4 bv = *(const float4*)(Wptr + (size_t)k0 * M);
        As[acol + 0][arow] = av.x;
        As[acol + 1][arow] = av.y;
        As[acol + 2][arow] = av.z;
        As[acol + 3][arow] = av.w;
        *(float4*)&Bs[brow][bcol] = bv;
        __syncthreads();
        #pragma unroll
        for (int k = 0; k < BK; k++) {
            float a[8], b[8];
            #pragma unroll
            for (int i = 0; i < 8; i++) a[i] = As[k][ty * 8 + i];
            #pragma unroll
            for (int j = 0; j < 8; j++) b[j] = Bs[k][tx * 8 + j];
            #pragma unroll
            for (int i = 0; i < 8; i++)
                #pragma unroll
                for (int j = 0; j < 8; j++)
                    acc[i][j] = fmaf(a[i], b[j], acc[i][j]);
        }
        __syncthreads();
    }

    #pragma unroll
    for (int i = 0; i < 8; i++) {
        int row = rowBase + ty * 8 + i;
        if (row >= nrow) break;
        #pragma unroll
        for (int j = 0; j < 8; j++) {
            int col = colBase + tx * 8 + j;
            float v = acc[i][j] + bias[col];
            float* cp = C + (size_t)row * M + col;
            if (EPI == EPI_ADD)       v += *cp;
            else if (EPI == EPI_GELU) v = v * normcdff(v);
            *cp = v;
        }
    }
}

// ----------------------------- output ---------------------------------------
__global__ void k_out(const float* __restrict__ h, float* __restrict__ out) {
    int i = blockIdx.x * blockDim.x + threadIdx.x;
    if (i < NN * DD) out[i] = h[i];
}

// ----------------------------- host driver ----------------------------------
static void run_attention(const float* qkv, unsigned* menc, float* den,
                          float* num, float* att,
                          const int* src, const int* dst, int ne) {
    k_att_init<<<cdiv(NP1 * DD, 256), 256>>>(num, menc, den);
    int blk = cdiv(ne * 32, 256);
    k_att_score<<<blk, 256>>>(qkv, menc, src, dst, ne);
    k_att_accum<<<blk, 256>>>(qkv, menc, den, num, src, dst, ne);
    k_att_final<<<cdiv(NP1 * DD, 256), 256>>>(num, den, att);
}

extern "C" void kernel_launch(void* const* d_in, const int* in_sizes, int n_in,
                              void* d_out, int out_size) {
    const float* x        = (const float*)d_in[0];
    const int*   ei       = (const int*)d_in[1];
    const int*   eei      = (const int*)d_in[2];
    const float* Wqkv_loc = (const float*)d_in[3];
    const float* bqkv_loc = (const float*)d_in[4];
    const float* Wo_loc   = (const float*)d_in[5];
    const float* bo_loc   = (const float*)d_in[6];
    const float* Wqkv_exp = (const float*)d_in[7];
    const float* bqkv_exp = (const float*)d_in[8];
    const float* Wo_exp   = (const float*)d_in[9];
    const float* bo_exp   = (const float*)d_in[10];
    const float* ln_g     = (const float*)d_in[11];
    const float* ln_b     = (const float*)d_in[12];
    const float* W1       = (const float*)d_in[13];
    const float* b1       = (const float*)d_in[14];
    const float* W2       = (const float*)d_in[15];
    const float* b2       = (const float*)d_in[16];
    int EE = in_sizes[2] / 2;   // expander edge count (80004)

    float *h, *sum, *qkv0, *qkv1, *num0, *num1, *att0, *att1, *ffn;
    float *den0, *den1;
    unsigned *menc0, *menc1;
    int *lsrc, *ldst;
    cudaGetSymbolAddress((void**)&h,     g_h);
    cudaGetSymbolAddress((void**)&sum,   g_sum);
    cudaGetSymbolAddress((void**)&qkv0,  g_qkv0);
    cudaGetSymbolAddress((void**)&qkv1,  g_qkv1);
    cudaGetSymbolAddress((void**)&num0,  g_num0);
    cudaGetSymbolAddress((void**)&num1,  g_num1);
    cudaGetSymbolAddress((void**)&att0,  g_att0);
    cudaGetSymbolAddress((void**)&att1,  g_att1);
    cudaGetSymbolAddress((void**)&ffn,   g_ffn);
    cudaGetSymbolAddress((void**)&menc0, g_menc0);
    cudaGetSymbolAddress((void**)&menc1, g_menc1);
    cudaGetSymbolAddress((void**)&den0,  g_den0);
    cudaGetSymbolAddress((void**)&den1,  g_den1);
    cudaGetSymbolAddress((void**)&lsrc,  g_src);
    cudaGetSymbolAddress((void**)&ldst,  g_dst);

    k_build_h<<<cdiv(NP1 * DD, 256), 256>>>(x, h);
    k_build_edges<<<cdiv(ELOC, 256), 256>>>(ei, lsrc, ldst);

    dim3 g_qkv(QKVW / BN, cdiv(NP1, BM));
    dim3 g_wo (DD   / BN, cdiv(NP1, BM));
    dim3 g_w1 (FFH  / BN, cdiv(NP1, BM));
    dim3 g_w2 (DD   / BN, cdiv(NP1, BM));

    for (int l = 0; l < NL; l++) {
        const float* Wq0 = Wqkv_loc + (size_t)l * DD * QKVW;
        const float* bq0 = bqkv_loc + (size_t)l * QKVW;
        const float* Wq1 = Wqkv_exp + (size_t)l * DD * QKVW;
        const float* bq1 = bqkv_exp + (size_t)l * QKVW;
        const float* Wo0 = Wo_loc + (size_t)l * DD * DD;
        const float* bo0 = bo_loc + (size_t)l * DD;
        const float* Wo1 = Wo_exp + (size_t)l * DD * DD;
        const float* bo1 = bo_exp + (size_t)l * DD;

        // QKV projections
        k_sgemm<EPI_STORE><<<g_qkv, 256>>>(h, Wq0, bq0, qkv0, NP1, DD, QKVW);
        k_sgemm<EPI_STORE><<<g_qkv, 256>>>(h, Wq1, bq1, qkv1, NP1, DD, QKVW);

        // sparse attentions
        run_attention(qkv0, menc0, den0, num0, att0, lsrc, ldst, ELOC);
        run_attention(qkv1, menc1, den1, num1, att1, eei, eei + EE, EE);

        // sum = residual + loc@Wo + exp@Wo
        k_copy<<<cdiv(NP1 * DD, 256), 256>>>(h, sum, NP1 * DD);
        k_sgemm<EPI_ADD><<<g_wo, 256>>>(att0, Wo0, bo0, sum, NP1, DD, DD);
        k_sgemm<EPI_ADD><<<g_wo, 256>>>(att1, Wo1, bo1, sum, NP1, DD, DD);

        // layernorm -> h
        k_layernorm<<<NP1, DD>>>(sum, ln_g + (size_t)l * DD,
                                 ln_b + (size_t)l * DD, h);

        // FFN: h += gelu(h@W1+b1)@W2 + b2
        k_sgemm<EPI_GELU><<<g_w1, 256>>>(h, W1 + (size_t)l * DD * FFH,
                                         b1 + (size_t)l * FFH, ffn, NP1, DD, FFH);
        k_sgemm<EPI_ADD><<<g_w2, 256>>>(ffn, W2 + (size_t)l * FFH * DD,
                                        b2 + (size_t)l * DD, h, NP1, FFH, DD);
    }

    k_out<<<cdiv(NN * DD, 256), 256>>>(h, (float*)d_out);
}